// round 10
// baseline (speedup 1.0000x reference)
#include <cuda_runtime.h>
#include <math.h>
#include <stdint.h>

// Problem constants
#define BATCH   4
#define SEQLEN  2048
#define DMODEL  1024
#define NHEAD   16
#define HEADDIM 64
#define MROWS   (BATCH * SEQLEN)   // 8192

// Scratch (device globals: no allocation allowed in kernel_launch)
__device__ float g_q[(size_t)BATCH * NHEAD * SEQLEN * HEADDIM];    // [B,H,L,hd]
__device__ float g_k[(size_t)BATCH * NHEAD * SEQLEN * HEADDIM];
__device__ float g_v[(size_t)BATCH * NHEAD * SEQLEN * HEADDIM];
__device__ float g_attn[(size_t)MROWS * DMODEL];                   // [B,L,H*hd]

// ---------------------------------------------------------------------------
// TF32 mma helpers
// ---------------------------------------------------------------------------
__device__ __forceinline__ uint32_t f2tf32(float f) {
    uint32_t u;
    asm("cvt.rna.tf32.f32 %0, %1;" : "=r"(u) : "f"(f));
    return u;
}

__device__ __forceinline__ void mma_tf32(float* d, const uint32_t* a,
                                         uint32_t b0, uint32_t b1) {
    asm volatile(
        "mma.sync.aligned.m16n8k8.row.col.f32.tf32.tf32.f32 "
        "{%0,%1,%2,%3}, {%4,%5,%6,%7}, {%8,%9}, {%0,%1,%2,%3};\n"
        : "+f"(d[0]), "+f"(d[1]), "+f"(d[2]), "+f"(d[3])
        : "r"(a[0]), "r"(a[1]), "r"(a[2]), "r"(a[3]), "r"(b0), "r"(b1));
}

// ---------------------------------------------------------------------------
// TF32 tensor-core GEMM (proven config: 256 thr, 8 warps 2m x 4n,
// warp tile 64x32, BK=32).  C[m,n] = sum_k A[m,k]*W[n,k] + bias[n]
// ---------------------------------------------------------------------------
__global__ __launch_bounds__(256) void gemm_tf32(const float* __restrict__ A_in,
                                                 const float* __restrict__ W,
                                                 const float* __restrict__ bias,
                                                 float* __restrict__ C_out,
                                                 int sel)
{
    __shared__ float As[128][36];
    __shared__ float Ws[128][36];

    const int K = DMODEL;
    const float* A = (sel == 3) ? g_attn : A_in;
    float* C;
    if (sel == 0)      C = g_q;
    else if (sel == 1) C = g_k;
    else if (sel == 2) C = g_v;
    else               C = C_out;

    const int tid  = threadIdx.x;
    const int w    = tid >> 5;
    const int lane = tid & 31;
    const int g    = lane >> 2;
    const int q    = lane & 3;
    const int wm   = (w & 1) * 64;
    const int wn   = (w >> 1) * 32;

    const int m0 = blockIdx.y * 128;
    const int n0 = blockIdx.x * 128;

    const float* Aptr = A + (size_t)m0 * K;
    const float* Wptr = W + (size_t)n0 * K;

    int ld_row[4], ld_c4[4];
#pragma unroll
    for (int i = 0; i < 4; i++) {
        int idx = tid + i * 256;
        ld_row[i] = idx >> 3;
        ld_c4[i]  = (idx & 7) * 4;
    }

    float acc[4][4][4];
#pragma unroll
    for (int mi = 0; mi < 4; mi++)
#pragma unroll
        for (int nj = 0; nj < 4; nj++)
#pragma unroll
            for (int c = 0; c < 4; c++) acc[mi][nj][c] = 0.0f;

    float4 pa[4], pw[4];
#pragma unroll
    for (int i = 0; i < 4; i++) {
        pa[i] = *reinterpret_cast<const float4*>(Aptr + (size_t)ld_row[i] * K + ld_c4[i]);
        pw[i] = *reinterpret_cast<const float4*>(Wptr + (size_t)ld_row[i] * K + ld_c4[i]);
    }

    for (int kt = 0; kt < K; kt += 32) {
#pragma unroll
        for (int i = 0; i < 4; i++) {
            float4 a = pa[i], t;
            t.x = __uint_as_float(f2tf32(a.x));
            t.y = __uint_as_float(f2tf32(a.y));
            t.z = __uint_as_float(f2tf32(a.z));
            t.w = __uint_as_float(f2tf32(a.w));
            *reinterpret_cast<float4*>(&As[ld_row[i]][ld_c4[i]]) = t;
            float4 b = pw[i];
            t.x = __uint_as_float(f2tf32(b.x));
            t.y = __uint_as_float(f2tf32(b.y));
            t.z = __uint_as_float(f2tf32(b.z));
            t.w = __uint_as_float(f2tf32(b.w));
            *reinterpret_cast<float4*>(&Ws[ld_row[i]][ld_c4[i]]) = t;
        }
        __syncthreads();

        if (kt + 32 < K) {
#pragma unroll
            for (int i = 0; i < 4; i++) {
                pa[i] = *reinterpret_cast<const float4*>(
                    Aptr + (size_t)ld_row[i] * K + kt + 32 + ld_c4[i]);
                pw[i] = *reinterpret_cast<const float4*>(
                    Wptr + (size_t)ld_row[i] * K + kt + 32 + ld_c4[i]);
            }
        }

#pragma unroll
        for (int kc = 0; kc < 4; kc++) {
            const int k0 = kc * 8;
            uint32_t a[4][4];
#pragma unroll
            for (int mi = 0; mi < 4; mi++) {
                int r = wm + mi * 16;
                a[mi][0] = __float_as_uint(As[r + g][k0 + q]);
                a[mi][1] = __float_as_uint(As[r + 8 + g][k0 + q]);
                a[mi][2] = __float_as_uint(As[r + g][k0 + q + 4]);
                a[mi][3] = __float_as_uint(As[r + 8 + g][k0 + q + 4]);
            }
            uint32_t b[4][2];
#pragma unroll
            for (int nj = 0; nj < 4; nj++) {
                int bn = wn + nj * 8;
                b[nj][0] = __float_as_uint(Ws[bn + g][k0 + q]);
                b[nj][1] = __float_as_uint(Ws[bn + g][k0 + q + 4]);
            }
#pragma unroll
            for (int mi = 0; mi < 4; mi++)
#pragma unroll
                for (int nj = 0; nj < 4; nj++)
                    mma_tf32(acc[mi][nj], a[mi], b[nj][0], b[nj][1]);
        }
        __syncthreads();
    }

    float bn_[4][2];
#pragma unroll
    for (int nj = 0; nj < 4; nj++) {
        int cn = n0 + wn + nj * 8 + 2 * q;
        bn_[nj][0] = bias[cn];
        bn_[nj][1] = bias[cn + 1];
    }

#pragma unroll
    for (int nj = 0; nj < 4; nj++) {
        int cn = n0 + wn + nj * 8 + 2 * q;
#pragma unroll
        for (int mi = 0; mi < 4; mi++) {
#pragma unroll
            for (int rr = 0; rr < 2; rr++) {
                int m = m0 + wm + mi * 16 + g + rr * 8;
                float2 v = make_float2(acc[mi][nj][rr * 2 + 0] + bn_[nj][0],
                                       acc[mi][nj][rr * 2 + 1] + bn_[nj][1]);
                if (sel <= 2) {
                    int h_ = cn >> 6;
                    int d_ = cn & 63;
                    int b_ = m >> 11, l_ = m & 2047;
                    *reinterpret_cast<float2*>(
                        C + (((size_t)(b_ * NHEAD + h_)) * SEQLEN + l_) * HEADDIM + d_) = v;
                } else {
                    *reinterpret_cast<float2*>(C + (size_t)m * DMODEL + cn) = v;
                }
            }
        }
    }
}

// ---------------------------------------------------------------------------
// RoPE pre-pass: rotate g_q (with 1/8 scale folded) and g_k in place.
// ---------------------------------------------------------------------------
__global__ __launch_bounds__(256) void rope_kernel()
{
    int idx = blockIdx.x * 256 + threadIdx.x;
    int d  = idx & 31;
    int l  = (idx >> 5) & (SEQLEN - 1);
    int bh = idx >> 16;
    size_t base = ((size_t)bh * SEQLEN + l) * HEADDIM;

    float invf = __expf(-(float)d * (9.210340371976184f / 32.0f));
    float sn, cs;
    sincosf((float)l * invf, &sn, &cs);

    float q1 = g_q[base + d], q2 = g_q[base + d + 32];
    g_q[base + d]      = (q1 * cs - q2 * sn) * 0.125f;
    g_q[base + d + 32] = (q2 * cs + q1 * sn) * 0.125f;

    float k1 = g_k[base + d], k2 = g_k[base + d + 32];
    g_k[base + d]      = k1 * cs - k2 * sn;
    g_k[base + d + 32] = k2 * cs + k1 * sn;
}

// ---------------------------------------------------------------------------
// Flash attention, tf32 mma, RoPE precomputed.
// Grid: (L/128, B*H). Block: 256 threads (8 warps), 1 m-frag per warp.
// Paired K/V smem layouts (vectorized stores, B-frag = one LDS.64).
// P transpose via warp-private smem (replaces 64-shfl chain):
//   Pw[16][72] per warp; STS.64 phase banks 4g+q+4n (bij.), LDS.32 banks 8g+q.
// Dynamic smem: K/V 8960 fl + P 8*16*72 fl = 18176 floats = 72704 B.
// ---------------------------------------------------------------------------
__global__ __launch_bounds__(256, 2) void attn_mma_kernel()
{
    extern __shared__ float smem[];
    float (*Qs)[68] = (float(*)[68])smem;            // staging: 128*68 = 8704 ok
    float* Kbase = smem;                              // K pairs: 64 rows x 72 fl
    float* Vbase = smem + 64 * 72;                    // V pairs: 32 rows x 136 fl
    float* Pall  = smem + 64 * 72 + 32 * 136;         // P: 8 warps x 16 x 72 fl

    const int tid  = threadIdx.x;
    const int w    = tid >> 5;
    const int lane = tid & 31;
    const int g    = lane >> 2;
    const int q    = lane & 3;

    const int bh = blockIdx.y;
    const int b_ = bh >> 4;
    const int h_ = bh & 15;
    const int q0 = blockIdx.x * 128;

    float* Pw = Pall + w * (16 * 72);

    const float* Qg = g_q + (size_t)bh * SEQLEN * HEADDIM;
    const float* Kg = g_k + (size_t)bh * SEQLEN * HEADDIM;
    const float* Vg = g_v + (size_t)bh * SEQLEN * HEADDIM;

    // ---- Load Q tile [128][64] (RoPE'd + scaled) ----
#pragma unroll
    for (int i = 0; i < 8; i++) {
        int idx = tid + i * 256;
        int r = idx >> 4;
        int cv = (idx & 15) * 4;
        float4 v = *reinterpret_cast<const float4*>(Qg + (size_t)(q0 + r) * HEADDIM + cv);
        Qs[r][cv + 0] = v.x; Qs[r][cv + 1] = v.y;
        Qs[r][cv + 2] = v.z; Qs[r][cv + 3] = v.w;
    }
    __syncthreads();

    // ---- Extract Q A-fragment (1 m-frag per warp) ----
    uint32_t aq[8][4];
    {
        int row0 = w * 16 + g;
#pragma unroll
        for (int kc = 0; kc < 8; kc++) {
            int c0 = kc * 8 + q;
            aq[kc][0] = f2tf32(Qs[row0][c0]);
            aq[kc][1] = f2tf32(Qs[row0 + 8][c0]);
            aq[kc][2] = f2tf32(Qs[row0][c0 + 4]);
            aq[kc][3] = f2tf32(Qs[row0 + 8][c0 + 4]);
        }
    }

    float o[8][4];
    float mA = -INFINITY, mB = -INFINITY, lA = 0.0f, lB = 0.0f;
#pragma unroll
    for (int n = 0; n < 8; n++)
#pragma unroll
        for (int c = 0; c < 4; c++) o[n][c] = 0.0f;

    for (int kk = 0; kk < 32; kk++) {
        const int kv0 = kk * 64;
        __syncthreads();   // kk=0: Q frags extracted; kk>0: prior mma reads done

        // ---- K tile: pair columns (d, d+4). 1024 tasks across 256 thr. ----
#pragma unroll
        for (int i = 0; i < 4; i++) {
            int idx = tid + i * 256;
            int r  = idx >> 4;           // 0..63
            int kc = (idx >> 1) & 7;     // 0..7
            int h  = idx & 1;            // q-pair half
            const float* src = Kg + (size_t)(kv0 + r) * HEADDIM + kc * 8 + 2 * h;
            float2 a = *reinterpret_cast<const float2*>(src);
            float2 b = *reinterpret_cast<const float2*>(src + 4);
            float4 t;
            t.x = __uint_as_float(f2tf32(a.x));
            t.y = __uint_as_float(f2tf32(b.x));
            t.z = __uint_as_float(f2tf32(a.y));
            t.w = __uint_as_float(f2tf32(b.y));
            *reinterpret_cast<float4*>(&Kbase[r * 72 + kc * 8 + 4 * h]) = t;
        }
        // ---- V tile: pair rows (r, r+4). 1024 tasks. ----
#pragma unroll
        for (int i = 0; i < 4; i++) {
            int idx = tid + i * 256;
            int c2 = idx & 31;           // float2 column
            int rp = idx >> 5;           // 0..31: kc = rp>>2, q = rp&3
            int row = ((rp >> 2) << 3) + (rp & 3);
            const float* src = Vg + (size_t)(kv0 + row) * HEADDIM + 2 * c2;
            float2 a = *reinterpret_cast<const float2*>(src);
            float2 b = *reinterpret_cast<const float2*>(src + 4 * HEADDIM);
            float4 t;
            t.x = __uint_as_float(f2tf32(a.x));
            t.y = __uint_as_float(f2tf32(b.x));
            t.z = __uint_as_float(f2tf32(a.y));
            t.w = __uint_as_float(f2tf32(b.y));
            *reinterpret_cast<float4*>(&Vbase[rp * 136 + 4 * c2]) = t;
        }
        __syncthreads();

        // ---- S = Q . K^T (B-frag = one LDS.64) ----
        float s[8][4];
#pragma unroll
        for (int n = 0; n < 8; n++)
#pragma unroll
            for (int c = 0; c < 4; c++) s[n][c] = 0.0f;

#pragma unroll
        for (int n = 0; n < 8; n++) {
#pragma unroll
            for (int kc = 0; kc < 8; kc++) {
                float2 bb = *reinterpret_cast<const float2*>(
                    &Kbase[(n * 8 + g) * 72 + kc * 8 + 2 * q]);
                mma_tf32(s[n], aq[kc], __float_as_uint(bb.x), __float_as_uint(bb.y));
            }
        }

        // ---- Online softmax ----
        {
            float mxA = -1e30f, mxB = -1e30f;
#pragma unroll
            for (int n = 0; n < 8; n++) {
                mxA = fmaxf(mxA, fmaxf(s[n][0], s[n][1]));
                mxB = fmaxf(mxB, fmaxf(s[n][2], s[n][3]));
            }
            mxA = fmaxf(mxA, __shfl_xor_sync(0xffffffffu, mxA, 1));
            mxA = fmaxf(mxA, __shfl_xor_sync(0xffffffffu, mxA, 2));
            mxB = fmaxf(mxB, __shfl_xor_sync(0xffffffffu, mxB, 1));
            mxB = fmaxf(mxB, __shfl_xor_sync(0xffffffffu, mxB, 2));
            float mnA = fmaxf(mA, mxA);
            float mnB = fmaxf(mB, mxB);
            float cA = __expf(mA - mnA);
            float cB = __expf(mB - mnB);
            float rsA = 0.0f, rsB = 0.0f;
#pragma unroll
            for (int n = 0; n < 8; n++) {
                s[n][0] = __expf(s[n][0] - mnA); rsA += s[n][0];
                s[n][1] = __expf(s[n][1] - mnA); rsA += s[n][1];
                s[n][2] = __expf(s[n][2] - mnB); rsB += s[n][2];
                s[n][3] = __expf(s[n][3] - mnB); rsB += s[n][3];
                o[n][0] *= cA; o[n][1] *= cA;
                o[n][2] *= cB; o[n][3] *= cB;
            }
            rsA += __shfl_xor_sync(0xffffffffu, rsA, 1);
            rsA += __shfl_xor_sync(0xffffffffu, rsA, 2);
            rsB += __shfl_xor_sync(0xffffffffu, rsB, 1);
            rsB += __shfl_xor_sync(0xffffffffu, rsB, 2);
            lA = lA * cA + rsA; mA = mnA;
            lB = lB * cB + rsB; mB = mnB;
        }

        // ---- P transpose via warp-private smem (tf32-converted at store) ----
#pragma unroll
        for (int n = 0; n < 8; n++) {
            float2 v0, v1;
            v0.x = __uint_as_float(f2tf32(s[n][0]));
            v0.y = __uint_as_float(f2tf32(s[n][1]));
            v1.x = __uint_as_float(f2tf32(s[n][2]));
            v1.y = __uint_as_float(f2tf32(s[n][3]));
            *reinterpret_cast<float2*>(&Pw[g * 72 + n * 8 + 2 * q])       = v0;
            *reinterpret_cast<float2*>(&Pw[(g + 8) * 72 + n * 8 + 2 * q]) = v1;
        }
        __syncwarp();

        // ---- O += P . V : A-frags from Pw; V B-frag = one LDS.64 ----
#pragma unroll
        for (int kc = 0; kc < 8; kc++) {
            uint32_t ap[4];
            ap[0] = __float_as_uint(Pw[g * 72 + kc * 8 + q]);
            ap[1] = __float_as_uint(Pw[(g + 8) * 72 + kc * 8 + q]);
            ap[2] = __float_as_uint(Pw[g * 72 + kc * 8 + q + 4]);
            ap[3] = __float_as_uint(Pw[(g + 8) * 72 + kc * 8 + q + 4]);
#pragma unroll
            for (int n = 0; n < 8; n++) {
                float2 bb = *reinterpret_cast<const float2*>(
                    &Vbase[(kc * 4 + q) * 136 + 2 * (n * 8 + g)]);
                mma_tf32(o[n], ap, __float_as_uint(bb.x), __float_as_uint(bb.y));
            }
        }
    }

    // ---- Epilogue: normalize, write [B,L,H*hd] ----
    {
        float iA = 1.0f / lA;
        float iB = 1.0f / lB;
        int row0 = q0 + w * 16 + g;
#pragma unroll
        for (int n = 0; n < 8; n++) {
            int col = n * 8 + 2 * q;
            float2 r0v = make_float2(o[n][0] * iA, o[n][1] * iA);
            float2 r1v = make_float2(o[n][2] * iB, o[n][3] * iB);
            *reinterpret_cast<float2*>(
                g_attn + ((size_t)(b_ * SEQLEN + row0) * NHEAD + h_) * HEADDIM + col) = r0v;
            *reinterpret_cast<float2*>(
                g_attn + ((size_t)(b_ * SEQLEN + row0 + 8) * NHEAD + h_) * HEADDIM + col) = r1v;
        }
    }
}

// ---------------------------------------------------------------------------
#define ATTN_SMEM_BYTES ((64 * 72 + 32 * 136 + 8 * 16 * 72) * 4)   // 72704

extern "C" void kernel_launch(void* const* d_in, const int* in_sizes, int n_in,
                              void* d_out, int out_size)
{
    const float* x  = (const float*)d_in[0];
    const float* Wq = (const float*)d_in[1];
    const float* bq = (const float*)d_in[2];
    const float* Wk = (const float*)d_in[3];
    const float* bk = (const float*)d_in[4];
    const float* Wv = (const float*)d_in[5];
    const float* bv = (const float*)d_in[6];
    const float* Wo = (const float*)d_in[7];
    const float* bo = (const float*)d_in[8];
    float* out = (float*)d_out;

    cudaFuncSetAttribute(attn_mma_kernel,
                         cudaFuncAttributeMaxDynamicSharedMemorySize,
                         ATTN_SMEM_BYTES);

    dim3 ggrid(DMODEL / 128, MROWS / 128);   // (8, 64)
    gemm_tf32<<<ggrid, 256>>>(x, Wq, bq, nullptr, 0);
    gemm_tf32<<<ggrid, 256>>>(x, Wk, bk, nullptr, 1);
    gemm_tf32<<<ggrid, 256>>>(x, Wv, bv, nullptr, 2);

    rope_kernel<<<(BATCH * NHEAD * SEQLEN * 32) / 256, 256>>>();

    attn_mma_kernel<<<dim3(SEQLEN / 128, BATCH * NHEAD), 256, ATTN_SMEM_BYTES>>>();

    gemm_tf32<<<ggrid, 256>>>(nullptr, Wo, bo, out, 3);
}

// round 11
// speedup vs baseline: 1.0825x; 1.0825x over previous
#include <cuda_runtime.h>
#include <math.h>
#include <stdint.h>

// Problem constants
#define BATCH   4
#define SEQLEN  2048
#define DMODEL  1024
#define NHEAD   16
#define HEADDIM 64
#define MROWS   (BATCH * SEQLEN)   // 8192

// Scratch (device globals: no allocation allowed in kernel_launch)
__device__ float g_q[(size_t)BATCH * NHEAD * SEQLEN * HEADDIM];    // [B,H,L,hd]
__device__ float g_k[(size_t)BATCH * NHEAD * SEQLEN * HEADDIM];
__device__ float g_v[(size_t)BATCH * NHEAD * SEQLEN * HEADDIM];
__device__ float g_attn[(size_t)MROWS * DMODEL];                   // [B,L,H*hd]

// ---------------------------------------------------------------------------
// Helpers
// ---------------------------------------------------------------------------
__device__ __forceinline__ uint32_t f2tf32(float f) {
    uint32_t u;
    asm("cvt.rna.tf32.f32 %0, %1;" : "=r"(u) : "f"(f));
    return u;
}

__device__ __forceinline__ void mma_tf32(float* d, const uint32_t* a,
                                         uint32_t b0, uint32_t b1) {
    asm volatile(
        "mma.sync.aligned.m16n8k8.row.col.f32.tf32.tf32.f32 "
        "{%0,%1,%2,%3}, {%4,%5,%6,%7}, {%8,%9}, {%0,%1,%2,%3};\n"
        : "+f"(d[0]), "+f"(d[1]), "+f"(d[2]), "+f"(d[3])
        : "r"(a[0]), "r"(a[1]), "r"(a[2]), "r"(a[3]), "r"(b0), "r"(b1));
}

__device__ __forceinline__ void cp_async16(uint32_t smem_addr, const void* gptr) {
    asm volatile("cp.async.ca.shared.global [%0], [%1], 16;\n"
                 :: "r"(smem_addr), "l"(gptr));
}
#define CP_COMMIT() asm volatile("cp.async.commit_group;\n" ::: "memory")
#define CP_WAIT0()  asm volatile("cp.async.wait_group 0;\n" ::: "memory")

// ---------------------------------------------------------------------------
// TF32 GEMM with cp.async double-buffered pipeline.
// Block 128x128, BK=32, 256 threads (8 warps 2m x 4n), warp tile 64x32.
// Inputs stored to smem as RAW fp32 (tf32 mma truncates in HW).
// Dynamic smem: 2 buffers x (128x36 A + 128x36 W) = 73728 B.
// ---------------------------------------------------------------------------
#define GEMM_TILE_FL (128 * 36)
#define GEMM_SMEM_BYTES (4 * GEMM_TILE_FL * 4)   // 73728

__global__ __launch_bounds__(256) void gemm_tf32(const float* __restrict__ A_in,
                                                 const float* __restrict__ W,
                                                 const float* __restrict__ bias,
                                                 float* __restrict__ C_out,
                                                 int sel)
{
    extern __shared__ float sm[];
    float* Asm = sm;                         // 2 x 128x36
    float* Wsm = sm + 2 * GEMM_TILE_FL;      // 2 x 128x36

    const int K = DMODEL;
    const float* A = (sel == 3) ? g_attn : A_in;
    float* C;
    if (sel == 0)      C = g_q;
    else if (sel == 1) C = g_k;
    else if (sel == 2) C = g_v;
    else               C = C_out;

    const int tid  = threadIdx.x;
    const int w    = tid >> 5;
    const int lane = tid & 31;
    const int g    = lane >> 2;
    const int q    = lane & 3;
    const int wm   = (w & 1) * 64;
    const int wn   = (w >> 1) * 32;

    const int m0 = blockIdx.y * 128;
    const int n0 = blockIdx.x * 128;

    const float* Aptr = A + (size_t)m0 * K;
    const float* Wptr = W + (size_t)n0 * K;

    const uint32_t sA0 = (uint32_t)__cvta_generic_to_shared(Asm);
    const uint32_t sW0 = (uint32_t)__cvta_generic_to_shared(Wsm);

    int ld_row[4], ld_c4[4];
#pragma unroll
    for (int i = 0; i < 4; i++) {
        int idx = tid + i * 256;
        ld_row[i] = idx >> 3;
        ld_c4[i]  = (idx & 7) * 4;
    }

    float acc[4][4][4];
#pragma unroll
    for (int mi = 0; mi < 4; mi++)
#pragma unroll
        for (int nj = 0; nj < 4; nj++)
#pragma unroll
            for (int c = 0; c < 4; c++) acc[mi][nj][c] = 0.0f;

    // Prologue: issue copy for tile 0 into buffer 0
#pragma unroll
    for (int i = 0; i < 4; i++) {
        uint32_t off = (uint32_t)(ld_row[i] * 36 + ld_c4[i]) << 2;
        cp_async16(sA0 + off, Aptr + (size_t)ld_row[i] * K + ld_c4[i]);
        cp_async16(sW0 + off, Wptr + (size_t)ld_row[i] * K + ld_c4[i]);
    }
    CP_COMMIT();

    const int NIT = K / 32;   // 32
    for (int it = 0; it < NIT; it++) {
        CP_WAIT0();
        __syncthreads();

        // Issue next tile copy into the other buffer
        if (it + 1 < NIT) {
            int kt = (it + 1) * 32;
            uint32_t bufo = (uint32_t)(((it + 1) & 1) * GEMM_TILE_FL) << 2;
#pragma unroll
            for (int i = 0; i < 4; i++) {
                uint32_t off = bufo + ((uint32_t)(ld_row[i] * 36 + ld_c4[i]) << 2);
                cp_async16(sA0 + off, Aptr + (size_t)ld_row[i] * K + kt + ld_c4[i]);
                cp_async16(sW0 + off, Wptr + (size_t)ld_row[i] * K + kt + ld_c4[i]);
            }
            CP_COMMIT();
        }

        // Compute on current buffer
        const float* Ab = Asm + (it & 1) * GEMM_TILE_FL;
        const float* Wb = Wsm + (it & 1) * GEMM_TILE_FL;
#pragma unroll
        for (int kc = 0; kc < 4; kc++) {
            const int k0 = kc * 8;
            uint32_t a[4][4];
#pragma unroll
            for (int mi = 0; mi < 4; mi++) {
                int r = wm + mi * 16;
                a[mi][0] = __float_as_uint(Ab[(r + g) * 36 + k0 + q]);
                a[mi][1] = __float_as_uint(Ab[(r + 8 + g) * 36 + k0 + q]);
                a[mi][2] = __float_as_uint(Ab[(r + g) * 36 + k0 + q + 4]);
                a[mi][3] = __float_as_uint(Ab[(r + 8 + g) * 36 + k0 + q + 4]);
            }
            uint32_t b[4][2];
#pragma unroll
            for (int nj = 0; nj < 4; nj++) {
                int bn = wn + nj * 8;
                b[nj][0] = __float_as_uint(Wb[(bn + g) * 36 + k0 + q]);
                b[nj][1] = __float_as_uint(Wb[(bn + g) * 36 + k0 + q + 4]);
            }
#pragma unroll
            for (int mi = 0; mi < 4; mi++)
#pragma unroll
                for (int nj = 0; nj < 4; nj++)
                    mma_tf32(acc[mi][nj], a[mi], b[nj][0], b[nj][1]);
        }
        // No trailing sync: buffer (it&1) is only overwritten by the copy
        // issued in iteration it+1, which follows that iteration's barrier.
    }

    float bn_[4][2];
#pragma unroll
    for (int nj = 0; nj < 4; nj++) {
        int cn = n0 + wn + nj * 8 + 2 * q;
        bn_[nj][0] = bias[cn];
        bn_[nj][1] = bias[cn + 1];
    }

#pragma unroll
    for (int nj = 0; nj < 4; nj++) {
        int cn = n0 + wn + nj * 8 + 2 * q;
#pragma unroll
        for (int mi = 0; mi < 4; mi++) {
#pragma unroll
            for (int rr = 0; rr < 2; rr++) {
                int m = m0 + wm + mi * 16 + g + rr * 8;
                float2 v = make_float2(acc[mi][nj][rr * 2 + 0] + bn_[nj][0],
                                       acc[mi][nj][rr * 2 + 1] + bn_[nj][1]);
                if (sel <= 2) {
                    int h_ = cn >> 6;
                    int d_ = cn & 63;
                    int b_ = m >> 11, l_ = m & 2047;
                    *reinterpret_cast<float2*>(
                        C + (((size_t)(b_ * NHEAD + h_)) * SEQLEN + l_) * HEADDIM + d_) = v;
                } else {
                    *reinterpret_cast<float2*>(C + (size_t)m * DMODEL + cn) = v;
                }
            }
        }
    }
}

// ---------------------------------------------------------------------------
// RoPE pre-pass: rotate g_q (with 1/8 scale folded) and g_k in place.
// ---------------------------------------------------------------------------
__global__ __launch_bounds__(256) void rope_kernel()
{
    int idx = blockIdx.x * 256 + threadIdx.x;
    int d  = idx & 31;
    int l  = (idx >> 5) & (SEQLEN - 1);
    int bh = idx >> 16;
    size_t base = ((size_t)bh * SEQLEN + l) * HEADDIM;

    float invf = __expf(-(float)d * (9.210340371976184f / 32.0f));
    float sn, cs;
    sincosf((float)l * invf, &sn, &cs);

    float q1 = g_q[base + d], q2 = g_q[base + d + 32];
    g_q[base + d]      = (q1 * cs - q2 * sn) * 0.125f;
    g_q[base + d + 32] = (q2 * cs + q1 * sn) * 0.125f;

    float k1 = g_k[base + d], k2 = g_k[base + d + 32];
    g_k[base + d]      = k1 * cs - k2 * sn;
    g_k[base + d + 32] = k2 * cs + k1 * sn;
}

// ---------------------------------------------------------------------------
// Flash attention, tf32 mma, RoPE precomputed. (round-9 best config)
// Grid: (L/128, B*H). Block: 256 threads (8 warps), 1 m-frag per warp.
// Paired K/V smem layouts (vectorized stores, B-frag = one LDS.64).
// ---------------------------------------------------------------------------
__global__ __launch_bounds__(256, 2) void attn_mma_kernel()
{
    __shared__ float smem_all[64 * 72 + 32 * 136];   // 8960 floats = 35840 B
    float (*Qs)[68] = (float(*)[68])smem_all;        // staging: 128*68 = 8704 ok
    float* Kbase = smem_all;                         // K pairs: 64 rows x 72 fl
    float* Vbase = smem_all + 64 * 72;               // V pairs: 32 rows x 136 fl

    const int tid  = threadIdx.x;
    const int w    = tid >> 5;
    const int lane = tid & 31;
    const int g    = lane >> 2;
    const int q    = lane & 3;

    const int bh = blockIdx.y;
    const int b_ = bh >> 4;
    const int h_ = bh & 15;
    const int q0 = blockIdx.x * 128;

    const float* Qg = g_q + (size_t)bh * SEQLEN * HEADDIM;
    const float* Kg = g_k + (size_t)bh * SEQLEN * HEADDIM;
    const float* Vg = g_v + (size_t)bh * SEQLEN * HEADDIM;

    // ---- Load Q tile [128][64] (RoPE'd + scaled) ----
#pragma unroll
    for (int i = 0; i < 8; i++) {
        int idx = tid + i * 256;
        int r = idx >> 4;
        int cv = (idx & 15) * 4;
        float4 v = *reinterpret_cast<const float4*>(Qg + (size_t)(q0 + r) * HEADDIM + cv);
        Qs[r][cv + 0] = v.x; Qs[r][cv + 1] = v.y;
        Qs[r][cv + 2] = v.z; Qs[r][cv + 3] = v.w;
    }
    __syncthreads();

    // ---- Extract Q A-fragment (1 m-frag per warp) ----
    uint32_t aq[8][4];
    {
        int row0 = w * 16 + g;
#pragma unroll
        for (int kc = 0; kc < 8; kc++) {
            int c0 = kc * 8 + q;
            aq[kc][0] = f2tf32(Qs[row0][c0]);
            aq[kc][1] = f2tf32(Qs[row0 + 8][c0]);
            aq[kc][2] = f2tf32(Qs[row0][c0 + 4]);
            aq[kc][3] = f2tf32(Qs[row0 + 8][c0 + 4]);
        }
    }

    float o[8][4];
    float mA = -INFINITY, mB = -INFINITY, lA = 0.0f, lB = 0.0f;
#pragma unroll
    for (int n = 0; n < 8; n++)
#pragma unroll
        for (int c = 0; c < 4; c++) o[n][c] = 0.0f;

    for (int kk = 0; kk < 32; kk++) {
        const int kv0 = kk * 64;
        __syncthreads();   // kk=0: Q frags extracted; kk>0: prior mma reads done

        // ---- K tile: pair columns (d, d+4). 1024 tasks across 256 thr. ----
#pragma unroll
        for (int i = 0; i < 4; i++) {
            int idx = tid + i * 256;
            int r  = idx >> 4;           // 0..63
            int kc = (idx >> 1) & 7;     // 0..7
            int h  = idx & 1;            // q-pair half
            const float* src = Kg + (size_t)(kv0 + r) * HEADDIM + kc * 8 + 2 * h;
            float2 a = *reinterpret_cast<const float2*>(src);
            float2 b = *reinterpret_cast<const float2*>(src + 4);
            float4 t;
            t.x = __uint_as_float(f2tf32(a.x));
            t.y = __uint_as_float(f2tf32(b.x));
            t.z = __uint_as_float(f2tf32(a.y));
            t.w = __uint_as_float(f2tf32(b.y));
            *reinterpret_cast<float4*>(&Kbase[r * 72 + kc * 8 + 4 * h]) = t;
        }
        // ---- V tile: pair rows (r, r+4). 1024 tasks. ----
#pragma unroll
        for (int i = 0; i < 4; i++) {
            int idx = tid + i * 256;
            int c2 = idx & 31;           // float2 column
            int rp = idx >> 5;           // 0..31: kc = rp>>2, q = rp&3
            int row = ((rp >> 2) << 3) + (rp & 3);
            const float* src = Vg + (size_t)(kv0 + row) * HEADDIM + 2 * c2;
            float2 a = *reinterpret_cast<const float2*>(src);
            float2 b = *reinterpret_cast<const float2*>(src + 4 * HEADDIM);
            float4 t;
            t.x = __uint_as_float(f2tf32(a.x));
            t.y = __uint_as_float(f2tf32(b.x));
            t.z = __uint_as_float(f2tf32(a.y));
            t.w = __uint_as_float(f2tf32(b.y));
            *reinterpret_cast<float4*>(&Vbase[rp * 136 + 4 * c2]) = t;
        }
        __syncthreads();

        // ---- S = Q . K^T (B-frag = one LDS.64) ----
        float s[8][4];
#pragma unroll
        for (int n = 0; n < 8; n++)
#pragma unroll
            for (int c = 0; c < 4; c++) s[n][c] = 0.0f;

#pragma unroll
        for (int n = 0; n < 8; n++) {
#pragma unroll
            for (int kc = 0; kc < 8; kc++) {
                float2 bb = *reinterpret_cast<const float2*>(
                    &Kbase[(n * 8 + g) * 72 + kc * 8 + 2 * q]);
                mma_tf32(s[n], aq[kc], __float_as_uint(bb.x), __float_as_uint(bb.y));
            }
        }

        // ---- Online softmax ----
        {
            float mxA = -1e30f, mxB = -1e30f;
#pragma unroll
            for (int n = 0; n < 8; n++) {
                mxA = fmaxf(mxA, fmaxf(s[n][0], s[n][1]));
                mxB = fmaxf(mxB, fmaxf(s[n][2], s[n][3]));
            }
            mxA = fmaxf(mxA, __shfl_xor_sync(0xffffffffu, mxA, 1));
            mxA = fmaxf(mxA, __shfl_xor_sync(0xffffffffu, mxA, 2));
            mxB = fmaxf(mxB, __shfl_xor_sync(0xffffffffu, mxB, 1));
            mxB = fmaxf(mxB, __shfl_xor_sync(0xffffffffu, mxB, 2));
            float mnA = fmaxf(mA, mxA);
            float mnB = fmaxf(mB, mxB);
            float cA = __expf(mA - mnA);
            float cB = __expf(mB - mnB);
            float rsA = 0.0f, rsB = 0.0f;
#pragma unroll
            for (int n = 0; n < 8; n++) {
                s[n][0] = __expf(s[n][0] - mnA); rsA += s[n][0];
                s[n][1] = __expf(s[n][1] - mnA); rsA += s[n][1];
                s[n][2] = __expf(s[n][2] - mnB); rsB += s[n][2];
                s[n][3] = __expf(s[n][3] - mnB); rsB += s[n][3];
                o[n][0] *= cA; o[n][1] *= cA;
                o[n][2] *= cB; o[n][3] *= cB;
            }
            rsA += __shfl_xor_sync(0xffffffffu, rsA, 1);
            rsA += __shfl_xor_sync(0xffffffffu, rsA, 2);
            rsB += __shfl_xor_sync(0xffffffffu, rsB, 1);
            rsB += __shfl_xor_sync(0xffffffffu, rsB, 2);
            lA = lA * cA + rsA; mA = mnA;
            lB = lB * cB + rsB; mB = mnB;
        }

        // ---- O += P . V : P A-frags via shfl; V B-frag = one LDS.64 ----
        const int src0 = (g << 2) + (q >> 1);
        const int src1 = src0 + 2;
        const bool odd = (q & 1);
#pragma unroll
        for (int kc = 0; kc < 8; kc++) {
            uint32_t ap[4];
            float v00 = __shfl_sync(0xffffffffu, s[kc][0], src0);
            float v01 = __shfl_sync(0xffffffffu, s[kc][1], src0);
            float v02 = __shfl_sync(0xffffffffu, s[kc][2], src0);
            float v03 = __shfl_sync(0xffffffffu, s[kc][3], src0);
            float v10 = __shfl_sync(0xffffffffu, s[kc][0], src1);
            float v11 = __shfl_sync(0xffffffffu, s[kc][1], src1);
            float v12 = __shfl_sync(0xffffffffu, s[kc][2], src1);
            float v13 = __shfl_sync(0xffffffffu, s[kc][3], src1);
            ap[0] = f2tf32(odd ? v01 : v00);
            ap[1] = f2tf32(odd ? v03 : v02);
            ap[2] = f2tf32(odd ? v11 : v10);
            ap[3] = f2tf32(odd ? v13 : v12);
#pragma unroll
            for (int n = 0; n < 8; n++) {
                float2 bb = *reinterpret_cast<const float2*>(
                    &Vbase[(kc * 4 + q) * 136 + 2 * (n * 8 + g)]);
                mma_tf32(o[n], ap, __float_as_uint(bb.x), __float_as_uint(bb.y));
            }
        }
    }

    // ---- Epilogue: normalize, write [B,L,H*hd] ----
    {
        float iA = 1.0f / lA;
        float iB = 1.0f / lB;
        int row0 = q0 + w * 16 + g;
#pragma unroll
        for (int n = 0; n < 8; n++) {
            int col = n * 8 + 2 * q;
            float2 r0v = make_float2(o[n][0] * iA, o[n][1] * iA);
            float2 r1v = make_float2(o[n][2] * iB, o[n][3] * iB);
            *reinterpret_cast<float2*>(
                g_attn + ((size_t)(b_ * SEQLEN + row0) * NHEAD + h_) * HEADDIM + col) = r0v;
            *reinterpret_cast<float2*>(
                g_attn + ((size_t)(b_ * SEQLEN + row0 + 8) * NHEAD + h_) * HEADDIM + col) = r1v;
        }
    }
}

// ---------------------------------------------------------------------------
extern "C" void kernel_launch(void* const* d_in, const int* in_sizes, int n_in,
                              void* d_out, int out_size)
{
    const float* x  = (const float*)d_in[0];
    const float* Wq = (const float*)d_in[1];
    const float* bq = (const float*)d_in[2];
    const float* Wk = (const float*)d_in[3];
    const float* bk = (const float*)d_in[4];
    const float* Wv = (const float*)d_in[5];
    const float* bv = (const float*)d_in[6];
    const float* Wo = (const float*)d_in[7];
    const float* bo = (const float*)d_in[8];
    float* out = (float*)d_out;

    cudaFuncSetAttribute(gemm_tf32,
                         cudaFuncAttributeMaxDynamicSharedMemorySize,
                         GEMM_SMEM_BYTES);

    dim3 ggrid(DMODEL / 128, MROWS / 128);   // (8, 64)
    gemm_tf32<<<ggrid, 256, GEMM_SMEM_BYTES>>>(x, Wq, bq, nullptr, 0);
    gemm_tf32<<<ggrid, 256, GEMM_SMEM_BYTES>>>(x, Wk, bk, nullptr, 1);
    gemm_tf32<<<ggrid, 256, GEMM_SMEM_BYTES>>>(x, Wv, bv, nullptr, 2);

    rope_kernel<<<(BATCH * NHEAD * SEQLEN * 32) / 256, 256>>>();

    attn_mma_kernel<<<dim3(SEQLEN / 128, BATCH * NHEAD), 256>>>();

    gemm_tf32<<<ggrid, 256, GEMM_SMEM_BYTES>>>(nullptr, Wo, bo, out, 3);
}

// round 12
// speedup vs baseline: 1.3569x; 1.2535x over previous
#include <cuda_runtime.h>
#include <math.h>
#include <stdint.h>

// Problem constants
#define BATCH   4
#define SEQLEN  2048
#define DMODEL  1024
#define NHEAD   16
#define HEADDIM 64
#define MROWS   (BATCH * SEQLEN)   // 8192

// Scratch (device globals: no allocation allowed in kernel_launch)
__device__ float g_q[(size_t)BATCH * NHEAD * SEQLEN * HEADDIM];    // [B,H,L,hd]
__device__ float g_k[(size_t)BATCH * NHEAD * SEQLEN * HEADDIM];
__device__ float g_v[(size_t)BATCH * NHEAD * SEQLEN * HEADDIM];
__device__ float g_attn[(size_t)MROWS * DMODEL];                   // [B,L,H*hd]

// ---------------------------------------------------------------------------
// Helpers
// ---------------------------------------------------------------------------
__device__ __forceinline__ uint32_t f2tf32(float f) {
    uint32_t u;
    asm("cvt.rna.tf32.f32 %0, %1;" : "=r"(u) : "f"(f));
    return u;
}

// pack two f32 into f16x2: lo in lower half, hi in upper half
__device__ __forceinline__ uint32_t pack_f16x2(float lo, float hi) {
    uint32_t r;
    asm("cvt.rn.f16x2.f32 %0, %1, %2;" : "=r"(r) : "f"(hi), "f"(lo));
    return r;
}

__device__ __forceinline__ void mma_tf32(float* d, const uint32_t* a,
                                         uint32_t b0, uint32_t b1) {
    asm volatile(
        "mma.sync.aligned.m16n8k8.row.col.f32.tf32.tf32.f32 "
        "{%0,%1,%2,%3}, {%4,%5,%6,%7}, {%8,%9}, {%0,%1,%2,%3};\n"
        : "+f"(d[0]), "+f"(d[1]), "+f"(d[2]), "+f"(d[3])
        : "r"(a[0]), "r"(a[1]), "r"(a[2]), "r"(a[3]), "r"(b0), "r"(b1));
}

__device__ __forceinline__ void mma_f16(float* d, const uint32_t* a,
                                        uint32_t b0, uint32_t b1) {
    asm volatile(
        "mma.sync.aligned.m16n8k16.row.col.f32.f16.f16.f32 "
        "{%0,%1,%2,%3}, {%4,%5,%6,%7}, {%8,%9}, {%0,%1,%2,%3};\n"
        : "+f"(d[0]), "+f"(d[1]), "+f"(d[2]), "+f"(d[3])
        : "r"(a[0]), "r"(a[1]), "r"(a[2]), "r"(a[3]), "r"(b0), "r"(b1));
}

__device__ __forceinline__ void cp_async16(uint32_t smem_addr, const void* gptr) {
    asm volatile("cp.async.ca.shared.global [%0], [%1], 16;\n"
                 :: "r"(smem_addr), "l"(gptr));
}
#define CP_COMMIT() asm volatile("cp.async.commit_group;\n" ::: "memory")
#define CP_WAIT0()  asm volatile("cp.async.wait_group 0;\n" ::: "memory")

// ---------------------------------------------------------------------------
// TF32 GEMM with cp.async double-buffered pipeline. (round-11 best, unchanged)
// Block 128x128, BK=32, 256 threads (8 warps 2m x 4n), warp tile 64x32.
// ---------------------------------------------------------------------------
#define GEMM_TILE_FL (128 * 36)
#define GEMM_SMEM_BYTES (4 * GEMM_TILE_FL * 4)   // 73728

__global__ __launch_bounds__(256) void gemm_tf32(const float* __restrict__ A_in,
                                                 const float* __restrict__ W,
                                                 const float* __restrict__ bias,
                                                 float* __restrict__ C_out,
                                                 int sel)
{
    extern __shared__ float sm[];
    float* Asm = sm;
    float* Wsm = sm + 2 * GEMM_TILE_FL;

    const int K = DMODEL;
    const float* A = (sel == 3) ? g_attn : A_in;
    float* C;
    if (sel == 0)      C = g_q;
    else if (sel == 1) C = g_k;
    else if (sel == 2) C = g_v;
    else               C = C_out;

    const int tid  = threadIdx.x;
    const int w    = tid >> 5;
    const int lane = tid & 31;
    const int g    = lane >> 2;
    const int q    = lane & 3;
    const int wm   = (w & 1) * 64;
    const int wn   = (w >> 1) * 32;

    const int m0 = blockIdx.y * 128;
    const int n0 = blockIdx.x * 128;

    const float* Aptr = A + (size_t)m0 * K;
    const float* Wptr = W + (size_t)n0 * K;

    const uint32_t sA0 = (uint32_t)__cvta_generic_to_shared(Asm);
    const uint32_t sW0 = (uint32_t)__cvta_generic_to_shared(Wsm);

    int ld_row[4], ld_c4[4];
#pragma unroll
    for (int i = 0; i < 4; i++) {
        int idx = tid + i * 256;
        ld_row[i] = idx >> 3;
        ld_c4[i]  = (idx & 7) * 4;
    }

    float acc[4][4][4];
#pragma unroll
    for (int mi = 0; mi < 4; mi++)
#pragma unroll
        for (int nj = 0; nj < 4; nj++)
#pragma unroll
            for (int c = 0; c < 4; c++) acc[mi][nj][c] = 0.0f;

#pragma unroll
    for (int i = 0; i < 4; i++) {
        uint32_t off = (uint32_t)(ld_row[i] * 36 + ld_c4[i]) << 2;
        cp_async16(sA0 + off, Aptr + (size_t)ld_row[i] * K + ld_c4[i]);
        cp_async16(sW0 + off, Wptr + (size_t)ld_row[i] * K + ld_c4[i]);
    }
    CP_COMMIT();

    const int NIT = K / 32;
    for (int it = 0; it < NIT; it++) {
        CP_WAIT0();
        __syncthreads();

        if (it + 1 < NIT) {
            int kt = (it + 1) * 32;
            uint32_t bufo = (uint32_t)(((it + 1) & 1) * GEMM_TILE_FL) << 2;
#pragma unroll
            for (int i = 0; i < 4; i++) {
                uint32_t off = bufo + ((uint32_t)(ld_row[i] * 36 + ld_c4[i]) << 2);
                cp_async16(sA0 + off, Aptr + (size_t)ld_row[i] * K + kt + ld_c4[i]);
                cp_async16(sW0 + off, Wptr + (size_t)ld_row[i] * K + kt + ld_c4[i]);
            }
            CP_COMMIT();
        }

        const float* Ab = Asm + (it & 1) * GEMM_TILE_FL;
        const float* Wb = Wsm + (it & 1) * GEMM_TILE_FL;
#pragma unroll
        for (int kc = 0; kc < 4; kc++) {
            const int k0 = kc * 8;
            uint32_t a[4][4];
#pragma unroll
            for (int mi = 0; mi < 4; mi++) {
                int r = wm + mi * 16;
                a[mi][0] = __float_as_uint(Ab[(r + g) * 36 + k0 + q]);
                a[mi][1] = __float_as_uint(Ab[(r + 8 + g) * 36 + k0 + q]);
                a[mi][2] = __float_as_uint(Ab[(r + g) * 36 + k0 + q + 4]);
                a[mi][3] = __float_as_uint(Ab[(r + 8 + g) * 36 + k0 + q + 4]);
            }
            uint32_t b[4][2];
#pragma unroll
            for (int nj = 0; nj < 4; nj++) {
                int bn = wn + nj * 8;
                b[nj][0] = __float_as_uint(Wb[(bn + g) * 36 + k0 + q]);
                b[nj][1] = __float_as_uint(Wb[(bn + g) * 36 + k0 + q + 4]);
            }
#pragma unroll
            for (int mi = 0; mi < 4; mi++)
#pragma unroll
                for (int nj = 0; nj < 4; nj++)
                    mma_tf32(acc[mi][nj], a[mi], b[nj][0], b[nj][1]);
        }
    }

    float bn_[4][2];
#pragma unroll
    for (int nj = 0; nj < 4; nj++) {
        int cn = n0 + wn + nj * 8 + 2 * q;
        bn_[nj][0] = bias[cn];
        bn_[nj][1] = bias[cn + 1];
    }

#pragma unroll
    for (int nj = 0; nj < 4; nj++) {
        int cn = n0 + wn + nj * 8 + 2 * q;
#pragma unroll
        for (int mi = 0; mi < 4; mi++) {
#pragma unroll
            for (int rr = 0; rr < 2; rr++) {
                int m = m0 + wm + mi * 16 + g + rr * 8;
                float2 v = make_float2(acc[mi][nj][rr * 2 + 0] + bn_[nj][0],
                                       acc[mi][nj][rr * 2 + 1] + bn_[nj][1]);
                if (sel <= 2) {
                    int h_ = cn >> 6;
                    int d_ = cn & 63;
                    int b_ = m >> 11, l_ = m & 2047;
                    *reinterpret_cast<float2*>(
                        C + (((size_t)(b_ * NHEAD + h_)) * SEQLEN + l_) * HEADDIM + d_) = v;
                } else {
                    *reinterpret_cast<float2*>(C + (size_t)m * DMODEL + cn) = v;
                }
            }
        }
    }
}

// ---------------------------------------------------------------------------
// RoPE pre-pass: rotate g_q (with 1/8 scale folded) and g_k in place.
// ---------------------------------------------------------------------------
__global__ __launch_bounds__(256) void rope_kernel()
{
    int idx = blockIdx.x * 256 + threadIdx.x;
    int d  = idx & 31;
    int l  = (idx >> 5) & (SEQLEN - 1);
    int bh = idx >> 16;
    size_t base = ((size_t)bh * SEQLEN + l) * HEADDIM;

    float invf = __expf(-(float)d * (9.210340371976184f / 32.0f));
    float sn, cs;
    sincosf((float)l * invf, &sn, &cs);

    float q1 = g_q[base + d], q2 = g_q[base + d + 32];
    g_q[base + d]      = (q1 * cs - q2 * sn) * 0.125f;
    g_q[base + d + 32] = (q2 * cs + q1 * sn) * 0.125f;

    float k1 = g_k[base + d], k2 = g_k[base + d + 32];
    g_k[base + d]      = k1 * cs - k2 * sn;
    g_k[base + d + 32] = k2 * cs + k1 * sn;
}

// ---------------------------------------------------------------------------
// Flash attention, fp16 mma (m16n8k16, fp32 accum), RoPE precomputed.
// Grid: (L/128, B*H). Block: 256 threads (8 warps), 1 m-frag per warp.
// Kb[64][36] u32: d-adjacent fp16 pairs {K[c][2j], K[c][2j+1]}   (B-frag S)
// Vb[32][68] u32: row-adjacent fp16 pairs {V[2rp][d], V[2rp+1][d]} (B-frag PV)
// P A-frags: packed in-thread from S accumulator pairs (no transpose!).
// ---------------------------------------------------------------------------
__global__ __launch_bounds__(256, 2) void attn_mma_kernel()
{
    __shared__ float smem_all[128 * 68];              // staging 8704 fl (34816 B)
    float (*Qs)[68] = (float(*)[68])smem_all;
    uint32_t* Kb = (uint32_t*)smem_all;               // 64 x 36 u32 = 2304
    uint32_t* Vb = (uint32_t*)smem_all + 64 * 36;     // 32 x 68 u32 = 2176

    const int tid  = threadIdx.x;
    const int w    = tid >> 5;
    const int lane = tid & 31;
    const int g    = lane >> 2;
    const int q    = lane & 3;

    const int bh = blockIdx.y;
    const int b_ = bh >> 4;
    const int h_ = bh & 15;
    const int q0 = blockIdx.x * 128;

    const float* Qg = g_q + (size_t)bh * SEQLEN * HEADDIM;
    const float* Kg = g_k + (size_t)bh * SEQLEN * HEADDIM;
    const float* Vg = g_v + (size_t)bh * SEQLEN * HEADDIM;

    // ---- Load Q tile [128][64] (RoPE'd + scaled) into staging ----
#pragma unroll
    for (int i = 0; i < 8; i++) {
        int idx = tid + i * 256;
        int r = idx >> 4;
        int cv = (idx & 15) * 4;
        float4 v = *reinterpret_cast<const float4*>(Qg + (size_t)(q0 + r) * HEADDIM + cv);
        Qs[r][cv + 0] = v.x; Qs[r][cv + 1] = v.y;
        Qs[r][cv + 2] = v.z; Qs[r][cv + 3] = v.w;
    }
    __syncthreads();

    // ---- Extract Q A-fragments as fp16 pairs: aq[kc][4], kc over 4 k16-chunks
    uint32_t aq[4][4];
    {
        int row0 = w * 16 + g;
#pragma unroll
        for (int kc = 0; kc < 4; kc++) {
            int c0 = kc * 16 + 2 * q;
            aq[kc][0] = pack_f16x2(Qs[row0][c0],         Qs[row0][c0 + 1]);
            aq[kc][1] = pack_f16x2(Qs[row0 + 8][c0],     Qs[row0 + 8][c0 + 1]);
            aq[kc][2] = pack_f16x2(Qs[row0][c0 + 8],     Qs[row0][c0 + 9]);
            aq[kc][3] = pack_f16x2(Qs[row0 + 8][c0 + 8], Qs[row0 + 8][c0 + 9]);
        }
    }

    float o[8][4];
    float mA = -INFINITY, mB = -INFINITY, lA = 0.0f, lB = 0.0f;
#pragma unroll
    for (int n = 0; n < 8; n++)
#pragma unroll
        for (int c = 0; c < 4; c++) o[n][c] = 0.0f;

    for (int kk = 0; kk < 32; kk++) {
        const int kv0 = kk * 64;
        __syncthreads();   // kk=0: Q frags extracted; kk>0: prior mma reads done

        // ---- K tile -> Kb: pack d-adjacent pairs. 1024 tasks (float4 each).
#pragma unroll
        for (int i = 0; i < 4; i++) {
            int idx = tid + i * 256;
            int r = idx >> 4;            // 0..63
            int j = idx & 15;            // float4 index: d = 4j..4j+3
            float4 kv = *reinterpret_cast<const float4*>(
                Kg + (size_t)(kv0 + r) * HEADDIM + 4 * j);
            uint32_t p0 = pack_f16x2(kv.x, kv.y);
            uint32_t p1 = pack_f16x2(kv.z, kv.w);
            *reinterpret_cast<uint2*>(&Kb[r * 36 + 2 * j]) = make_uint2(p0, p1);
        }
        // ---- V tile -> Vb: pack row-adjacent pairs. 1024 tasks (float2 cols).
#pragma unroll
        for (int i = 0; i < 4; i++) {
            int idx = tid + i * 256;
            int c2 = idx & 31;           // d-pair: cols 2c2, 2c2+1
            int rp = idx >> 5;           // 0..31: rows 2rp, 2rp+1
            const float* src = Vg + (size_t)(kv0 + 2 * rp) * HEADDIM + 2 * c2;
            float2 r0v = *reinterpret_cast<const float2*>(src);
            float2 r1v = *reinterpret_cast<const float2*>(src + HEADDIM);
            uint32_t p0 = pack_f16x2(r0v.x, r1v.x);
            uint32_t p1 = pack_f16x2(r0v.y, r1v.y);
            *reinterpret_cast<uint2*>(&Vb[rp * 68 + 2 * c2]) = make_uint2(p0, p1);
        }
        __syncthreads();

        // ---- S = Q . K^T  (f16 m16n8k16: 32 mmas) ----
        float s[8][4];
#pragma unroll
        for (int n = 0; n < 8; n++)
#pragma unroll
            for (int c = 0; c < 4; c++) s[n][c] = 0.0f;

#pragma unroll
        for (int n = 0; n < 8; n++) {
#pragma unroll
            for (int kc = 0; kc < 4; kc++) {
                uint32_t b0 = Kb[(n * 8 + g) * 36 + kc * 8 + q];
                uint32_t b1 = Kb[(n * 8 + g) * 36 + kc * 8 + 4 + q];
                mma_f16(s[n], aq[kc], b0, b1);
            }
        }

        // ---- Online softmax ----
        {
            float mxA = -1e30f, mxB = -1e30f;
#pragma unroll
            for (int n = 0; n < 8; n++) {
                mxA = fmaxf(mxA, fmaxf(s[n][0], s[n][1]));
                mxB = fmaxf(mxB, fmaxf(s[n][2], s[n][3]));
            }
            mxA = fmaxf(mxA, __shfl_xor_sync(0xffffffffu, mxA, 1));
            mxA = fmaxf(mxA, __shfl_xor_sync(0xffffffffu, mxA, 2));
            mxB = fmaxf(mxB, __shfl_xor_sync(0xffffffffu, mxB, 1));
            mxB = fmaxf(mxB, __shfl_xor_sync(0xffffffffu, mxB, 2));
            float mnA = fmaxf(mA, mxA);
            float mnB = fmaxf(mB, mxB);
            float cA = __expf(mA - mnA);
            float cB = __expf(mB - mnB);
            float rsA = 0.0f, rsB = 0.0f;
#pragma unroll
            for (int n = 0; n < 8; n++) {
                s[n][0] = __expf(s[n][0] - mnA); rsA += s[n][0];
                s[n][1] = __expf(s[n][1] - mnA); rsA += s[n][1];
                s[n][2] = __expf(s[n][2] - mnB); rsB += s[n][2];
                s[n][3] = __expf(s[n][3] - mnB); rsB += s[n][3];
                o[n][0] *= cA; o[n][1] *= cA;
                o[n][2] *= cB; o[n][3] *= cB;
            }
            rsA += __shfl_xor_sync(0xffffffffu, rsA, 1);
            rsA += __shfl_xor_sync(0xffffffffu, rsA, 2);
            rsB += __shfl_xor_sync(0xffffffffu, rsB, 1);
            rsB += __shfl_xor_sync(0xffffffffu, rsB, 2);
            lA = lA * cA + rsA; mA = mnA;
            lB = lB * cB + rsB; mB = mnB;
        }

        // ---- P A-frags: pack accumulator pairs in-thread (NO transpose) ----
        uint32_t ap[4][4];
#pragma unroll
        for (int kc = 0; kc < 4; kc++) {
            ap[kc][0] = pack_f16x2(s[2 * kc][0],     s[2 * kc][1]);
            ap[kc][1] = pack_f16x2(s[2 * kc][2],     s[2 * kc][3]);
            ap[kc][2] = pack_f16x2(s[2 * kc + 1][0], s[2 * kc + 1][1]);
            ap[kc][3] = pack_f16x2(s[2 * kc + 1][2], s[2 * kc + 1][3]);
        }

        // ---- O += P . V  (f16 m16n8k16: 32 mmas) ----
#pragma unroll
        for (int n = 0; n < 8; n++) {
#pragma unroll
            for (int kc = 0; kc < 4; kc++) {
                uint32_t b0 = Vb[(kc * 8 + q) * 68 + n * 8 + g];
                uint32_t b1 = Vb[(kc * 8 + 4 + q) * 68 + n * 8 + g];
                mma_f16(o[n], ap[kc], b0, b1);
            }
        }
    }

    // ---- Epilogue: normalize, write [B,L,H*hd] ----
    {
        float iA = 1.0f / lA;
        float iB = 1.0f / lB;
        int row0 = q0 + w * 16 + g;
#pragma unroll
        for (int n = 0; n < 8; n++) {
            int col = n * 8 + 2 * q;
            float2 r0v = make_float2(o[n][0] * iA, o[n][1] * iA);
            float2 r1v = make_float2(o[n][2] * iB, o[n][3] * iB);
            *reinterpret_cast<float2*>(
                g_attn + ((size_t)(b_ * SEQLEN + row0) * NHEAD + h_) * HEADDIM + col) = r0v;
            *reinterpret_cast<float2*>(
                g_attn + ((size_t)(b_ * SEQLEN + row0 + 8) * NHEAD + h_) * HEADDIM + col) = r1v;
        }
    }
}

// ---------------------------------------------------------------------------
extern "C" void kernel_launch(void* const* d_in, const int* in_sizes, int n_in,
                              void* d_out, int out_size)
{
    const float* x  = (const float*)d_in[0];
    const float* Wq = (const float*)d_in[1];
    const float* bq = (const float*)d_in[2];
    const float* Wk = (const float*)d_in[3];
    const float* bk = (const float*)d_in[4];
    const float* Wv = (const float*)d_in[5];
    const float* bv = (const float*)d_in[6];
    const float* Wo = (const float*)d_in[7];
    const float* bo = (const float*)d_in[8];
    float* out = (float*)d_out;

    cudaFuncSetAttribute(gemm_tf32,
                         cudaFuncAttributeMaxDynamicSharedMemorySize,
                         GEMM_SMEM_BYTES);

    dim3 ggrid(DMODEL / 128, MROWS / 128);   // (8, 64)
    gemm_tf32<<<ggrid, 256, GEMM_SMEM_BYTES>>>(x, Wq, bq, nullptr, 0);
    gemm_tf32<<<ggrid, 256, GEMM_SMEM_BYTES>>>(x, Wk, bk, nullptr, 1);
    gemm_tf32<<<ggrid, 256, GEMM_SMEM_BYTES>>>(x, Wv, bv, nullptr, 2);

    rope_kernel<<<(BATCH * NHEAD * SEQLEN * 32) / 256, 256>>>();

    attn_mma_kernel<<<dim3(SEQLEN / 128, BATCH * NHEAD), 256>>>();

    gemm_tf32<<<ggrid, 256, GEMM_SMEM_BYTES>>>(nullptr, Wo, bo, out, 3);
}

// round 13
// speedup vs baseline: 1.6340x; 1.2042x over previous
#include <cuda_runtime.h>
#include <cuda_fp16.h>
#include <math.h>
#include <stdint.h>

// Problem constants
#define BATCH   4
#define SEQLEN  2048
#define DMODEL  1024
#define NHEAD   16
#define HEADDIM 64
#define MROWS   (BATCH * SEQLEN)   // 8192

// Scratch (device globals: no allocation allowed in kernel_launch)
__device__ float  g_q[(size_t)BATCH * NHEAD * SEQLEN * HEADDIM];   // [B,H,L,hd]
__device__ float  g_k[(size_t)BATCH * NHEAD * SEQLEN * HEADDIM];
__device__ float  g_v[(size_t)BATCH * NHEAD * SEQLEN * HEADDIM];
__device__ __half g_xh[(size_t)MROWS * DMODEL];                    // fp16 x
__device__ __half g_wh[4][(size_t)DMODEL * DMODEL];                // fp16 Wq,Wk,Wv,Wo
__device__ __half g_attn_h[(size_t)MROWS * DMODEL];                // fp16 attn out

// ---------------------------------------------------------------------------
// Helpers
// ---------------------------------------------------------------------------
// pack two f32 into f16x2: lo in lower half, hi in upper half
__device__ __forceinline__ uint32_t pack_f16x2(float lo, float hi) {
    uint32_t r;
    asm("cvt.rn.f16x2.f32 %0, %1, %2;" : "=r"(r) : "f"(hi), "f"(lo));
    return r;
}

__device__ __forceinline__ void mma_f16(float* d, const uint32_t* a,
                                        uint32_t b0, uint32_t b1) {
    asm volatile(
        "mma.sync.aligned.m16n8k16.row.col.f32.f16.f16.f32 "
        "{%0,%1,%2,%3}, {%4,%5,%6,%7}, {%8,%9}, {%0,%1,%2,%3};\n"
        : "+f"(d[0]), "+f"(d[1]), "+f"(d[2]), "+f"(d[3])
        : "r"(a[0]), "r"(a[1]), "r"(a[2]), "r"(a[3]), "r"(b0), "r"(b1));
}

__device__ __forceinline__ void cp_async16(uint32_t smem_addr, const void* gptr) {
    asm volatile("cp.async.ca.shared.global [%0], [%1], 16;\n"
                 :: "r"(smem_addr), "l"(gptr));
}
#define CP_COMMIT() asm volatile("cp.async.commit_group;\n" ::: "memory")
#define CP_WAIT0()  asm volatile("cp.async.wait_group 0;\n" ::: "memory")

// ---------------------------------------------------------------------------
// fp32 -> fp16 conversion (rn). Each thread converts 4 elements.
// ---------------------------------------------------------------------------
__global__ __launch_bounds__(256) void cvt_f16_kernel(const float* __restrict__ src,
                                                      __half* __restrict__ dst,
                                                      int n4)
{
    int i = blockIdx.x * 256 + threadIdx.x;
    if (i < n4) {
        float4 v = reinterpret_cast<const float4*>(src)[i];
        uint32_t p0 = pack_f16x2(v.x, v.y);
        uint32_t p1 = pack_f16x2(v.z, v.w);
        reinterpret_cast<uint2*>(dst)[i] = make_uint2(p0, p1);
    }
}

// ---------------------------------------------------------------------------
// FP16 GEMM with cp.async double-buffered pipeline.
// C[m,n] = sum_k A[m,k]*W[n,k] + bias[n];  A,W fp16 K-contiguous, acc fp32.
// Block 128x128, BK=32, 256 threads (8 warps 2m x 4n), warp tile 64x32.
// Smem rows: 32 halves = 16 u32 + pad -> stride 20 u32 (conflict-free frags).
// Static smem: 4 x 128 x 20 u32 = 40960 B.
// ---------------------------------------------------------------------------
#define GTILE_U32 (128 * 20)

__global__ __launch_bounds__(256) void gemm_f16(const __half* __restrict__ A_in,
                                                const __half* __restrict__ Wt,
                                                const float* __restrict__ bias,
                                                float* __restrict__ C_out,
                                                int sel)
{
    __shared__ uint32_t sm[4 * GTILE_U32];
    uint32_t* Asm = sm;
    uint32_t* Wsm = sm + 2 * GTILE_U32;

    const int K = DMODEL;
    const __half* A = (sel == 3) ? g_attn_h : A_in;
    float* C;
    if (sel == 0)      C = g_q;
    else if (sel == 1) C = g_k;
    else if (sel == 2) C = g_v;
    else               C = C_out;

    const int tid  = threadIdx.x;
    const int w    = tid >> 5;
    const int lane = tid & 31;
    const int g    = lane >> 2;
    const int q    = lane & 3;
    const int wm   = (w & 1) * 64;
    const int wn   = (w >> 1) * 32;

    const int m0 = blockIdx.y * 128;
    const int n0 = blockIdx.x * 128;

    const __half* Aptr = A  + (size_t)m0 * K;
    const __half* Wptr = Wt + (size_t)n0 * K;

    const uint32_t sA0 = (uint32_t)__cvta_generic_to_shared(Asm);
    const uint32_t sW0 = (uint32_t)__cvta_generic_to_shared(Wsm);

    // copy mapping: 512 16B-chunks per operand; idx = tid + i*256
    int ld_row[2], ld_ch[2];
#pragma unroll
    for (int i = 0; i < 2; i++) {
        int idx = tid + i * 256;
        ld_row[i] = idx >> 2;       // 0..127
        ld_ch[i]  = idx & 3;        // 16B chunk within 64B row
    }

    float acc[4][4][4];
#pragma unroll
    for (int mi = 0; mi < 4; mi++)
#pragma unroll
        for (int nj = 0; nj < 4; nj++)
#pragma unroll
            for (int c = 0; c < 4; c++) acc[mi][nj][c] = 0.0f;

    // Prologue: tile 0 into buffer 0
#pragma unroll
    for (int i = 0; i < 2; i++) {
        uint32_t off = (uint32_t)(ld_row[i] * 20 + ld_ch[i] * 4) << 2;
        cp_async16(sA0 + off, Aptr + (size_t)ld_row[i] * K + ld_ch[i] * 8);
        cp_async16(sW0 + off, Wptr + (size_t)ld_row[i] * K + ld_ch[i] * 8);
    }
    CP_COMMIT();

    const int NIT = K / 32;   // 32
    for (int it = 0; it < NIT; it++) {
        CP_WAIT0();
        __syncthreads();

        if (it + 1 < NIT) {
            int kt = (it + 1) * 32;
            uint32_t bufo = (uint32_t)(((it + 1) & 1) * GTILE_U32) << 2;
#pragma unroll
            for (int i = 0; i < 2; i++) {
                uint32_t off = bufo + ((uint32_t)(ld_row[i] * 20 + ld_ch[i] * 4) << 2);
                cp_async16(sA0 + off, Aptr + (size_t)ld_row[i] * K + kt + ld_ch[i] * 8);
                cp_async16(sW0 + off, Wptr + (size_t)ld_row[i] * K + kt + ld_ch[i] * 8);
            }
            CP_COMMIT();
        }

        const uint32_t* Ab = Asm + (it & 1) * GTILE_U32;
        const uint32_t* Wb = Wsm + (it & 1) * GTILE_U32;
#pragma unroll
        for (int kc = 0; kc < 2; kc++) {
            const int k0 = kc * 8;
            uint32_t a[4][4];
#pragma unroll
            for (int mi = 0; mi < 4; mi++) {
                int r = wm + mi * 16;
                a[mi][0] = Ab[(r + g) * 20 + k0 + q];
                a[mi][1] = Ab[(r + 8 + g) * 20 + k0 + q];
                a[mi][2] = Ab[(r + g) * 20 + k0 + q + 4];
                a[mi][3] = Ab[(r + 8 + g) * 20 + k0 + q + 4];
            }
            uint32_t b[4][2];
#pragma unroll
            for (int nj = 0; nj < 4; nj++) {
                int bn = wn + nj * 8;
                b[nj][0] = Wb[(bn + g) * 20 + k0 + q];
                b[nj][1] = Wb[(bn + g) * 20 + k0 + q + 4];
            }
#pragma unroll
            for (int mi = 0; mi < 4; mi++)
#pragma unroll
                for (int nj = 0; nj < 4; nj++)
                    mma_f16(acc[mi][nj], a[mi], b[nj][0], b[nj][1]);
        }
    }

    float bn_[4][2];
#pragma unroll
    for (int nj = 0; nj < 4; nj++) {
        int cn = n0 + wn + nj * 8 + 2 * q;
        bn_[nj][0] = bias[cn];
        bn_[nj][1] = bias[cn + 1];
    }

#pragma unroll
    for (int nj = 0; nj < 4; nj++) {
        int cn = n0 + wn + nj * 8 + 2 * q;
#pragma unroll
        for (int mi = 0; mi < 4; mi++) {
#pragma unroll
            for (int rr = 0; rr < 2; rr++) {
                int m = m0 + wm + mi * 16 + g + rr * 8;
                float2 v = make_float2(acc[mi][nj][rr * 2 + 0] + bn_[nj][0],
                                       acc[mi][nj][rr * 2 + 1] + bn_[nj][1]);
                if (sel <= 2) {
                    int h_ = cn >> 6;
                    int d_ = cn & 63;
                    int b_ = m >> 11, l_ = m & 2047;
                    *reinterpret_cast<float2*>(
                        C + (((size_t)(b_ * NHEAD + h_)) * SEQLEN + l_) * HEADDIM + d_) = v;
                } else {
                    *reinterpret_cast<float2*>(C + (size_t)m * DMODEL + cn) = v;
                }
            }
        }
    }
}

// ---------------------------------------------------------------------------
// RoPE pre-pass: rotate g_q (with 1/8 scale folded) and g_k in place.
// ---------------------------------------------------------------------------
__global__ __launch_bounds__(256) void rope_kernel()
{
    int idx = blockIdx.x * 256 + threadIdx.x;
    int d  = idx & 31;
    int l  = (idx >> 5) & (SEQLEN - 1);
    int bh = idx >> 16;
    size_t base = ((size_t)bh * SEQLEN + l) * HEADDIM;

    float invf = __expf(-(float)d * (9.210340371976184f / 32.0f));
    float sn, cs;
    sincosf((float)l * invf, &sn, &cs);

    float q1 = g_q[base + d], q2 = g_q[base + d + 32];
    g_q[base + d]      = (q1 * cs - q2 * sn) * 0.125f;
    g_q[base + d + 32] = (q2 * cs + q1 * sn) * 0.125f;

    float k1 = g_k[base + d], k2 = g_k[base + d + 32];
    g_k[base + d]      = k1 * cs - k2 * sn;
    g_k[base + d + 32] = k2 * cs + k1 * sn;
}

// ---------------------------------------------------------------------------
// Flash attention, fp16 mma (m16n8k16, fp32 accum), RoPE precomputed.
// (round-12 winning config; epilogue now writes fp16 g_attn_h)
// ---------------------------------------------------------------------------
__global__ __launch_bounds__(256, 2) void attn_mma_kernel()
{
    __shared__ float smem_all[128 * 68];              // staging 8704 fl (34816 B)
    float (*Qs)[68] = (float(*)[68])smem_all;
    uint32_t* Kb = (uint32_t*)smem_all;               // 64 x 36 u32
    uint32_t* Vb = (uint32_t*)smem_all + 64 * 36;     // 32 x 68 u32

    const int tid  = threadIdx.x;
    const int w    = tid >> 5;
    const int lane = tid & 31;
    const int g    = lane >> 2;
    const int q    = lane & 3;

    const int bh = blockIdx.y;
    const int b_ = bh >> 4;
    const int h_ = bh & 15;
    const int q0 = blockIdx.x * 128;

    const float* Qg = g_q + (size_t)bh * SEQLEN * HEADDIM;
    const float* Kg = g_k + (size_t)bh * SEQLEN * HEADDIM;
    const float* Vg = g_v + (size_t)bh * SEQLEN * HEADDIM;

    // ---- Load Q tile [128][64] (RoPE'd + scaled) into staging ----
#pragma unroll
    for (int i = 0; i < 8; i++) {
        int idx = tid + i * 256;
        int r = idx >> 4;
        int cv = (idx & 15) * 4;
        float4 v = *reinterpret_cast<const float4*>(Qg + (size_t)(q0 + r) * HEADDIM + cv);
        Qs[r][cv + 0] = v.x; Qs[r][cv + 1] = v.y;
        Qs[r][cv + 2] = v.z; Qs[r][cv + 3] = v.w;
    }
    __syncthreads();

    // ---- Extract Q A-fragments as fp16 pairs ----
    uint32_t aq[4][4];
    {
        int row0 = w * 16 + g;
#pragma unroll
        for (int kc = 0; kc < 4; kc++) {
            int c0 = kc * 16 + 2 * q;
            aq[kc][0] = pack_f16x2(Qs[row0][c0],         Qs[row0][c0 + 1]);
            aq[kc][1] = pack_f16x2(Qs[row0 + 8][c0],     Qs[row0 + 8][c0 + 1]);
            aq[kc][2] = pack_f16x2(Qs[row0][c0 + 8],     Qs[row0][c0 + 9]);
            aq[kc][3] = pack_f16x2(Qs[row0 + 8][c0 + 8], Qs[row0 + 8][c0 + 9]);
        }
    }

    float o[8][4];
    float mA = -INFINITY, mB = -INFINITY, lA = 0.0f, lB = 0.0f;
#pragma unroll
    for (int n = 0; n < 8; n++)
#pragma unroll
        for (int c = 0; c < 4; c++) o[n][c] = 0.0f;

    for (int kk = 0; kk < 32; kk++) {
        const int kv0 = kk * 64;
        __syncthreads();

        // ---- K tile -> Kb: pack d-adjacent pairs ----
#pragma unroll
        for (int i = 0; i < 4; i++) {
            int idx = tid + i * 256;
            int r = idx >> 4;
            int j = idx & 15;
            float4 kv = *reinterpret_cast<const float4*>(
                Kg + (size_t)(kv0 + r) * HEADDIM + 4 * j);
            uint32_t p0 = pack_f16x2(kv.x, kv.y);
            uint32_t p1 = pack_f16x2(kv.z, kv.w);
            *reinterpret_cast<uint2*>(&Kb[r * 36 + 2 * j]) = make_uint2(p0, p1);
        }
        // ---- V tile -> Vb: pack row-adjacent pairs ----
#pragma unroll
        for (int i = 0; i < 4; i++) {
            int idx = tid + i * 256;
            int c2 = idx & 31;
            int rp = idx >> 5;
            const float* src = Vg + (size_t)(kv0 + 2 * rp) * HEADDIM + 2 * c2;
            float2 r0v = *reinterpret_cast<const float2*>(src);
            float2 r1v = *reinterpret_cast<const float2*>(src + HEADDIM);
            uint32_t p0 = pack_f16x2(r0v.x, r1v.x);
            uint32_t p1 = pack_f16x2(r0v.y, r1v.y);
            *reinterpret_cast<uint2*>(&Vb[rp * 68 + 2 * c2]) = make_uint2(p0, p1);
        }
        __syncthreads();

        // ---- S = Q . K^T ----
        float s[8][4];
#pragma unroll
        for (int n = 0; n < 8; n++)
#pragma unroll
            for (int c = 0; c < 4; c++) s[n][c] = 0.0f;

#pragma unroll
        for (int n = 0; n < 8; n++) {
#pragma unroll
            for (int kc = 0; kc < 4; kc++) {
                uint32_t b0 = Kb[(n * 8 + g) * 36 + kc * 8 + q];
                uint32_t b1 = Kb[(n * 8 + g) * 36 + kc * 8 + 4 + q];
                mma_f16(s[n], aq[kc], b0, b1);
            }
        }

        // ---- Online softmax ----
        {
            float mxA = -1e30f, mxB = -1e30f;
#pragma unroll
            for (int n = 0; n < 8; n++) {
                mxA = fmaxf(mxA, fmaxf(s[n][0], s[n][1]));
                mxB = fmaxf(mxB, fmaxf(s[n][2], s[n][3]));
            }
            mxA = fmaxf(mxA, __shfl_xor_sync(0xffffffffu, mxA, 1));
            mxA = fmaxf(mxA, __shfl_xor_sync(0xffffffffu, mxA, 2));
            mxB = fmaxf(mxB, __shfl_xor_sync(0xffffffffu, mxB, 1));
            mxB = fmaxf(mxB, __shfl_xor_sync(0xffffffffu, mxB, 2));
            float mnA = fmaxf(mA, mxA);
            float mnB = fmaxf(mB, mxB);
            float cA = __expf(mA - mnA);
            float cB = __expf(mB - mnB);
            float rsA = 0.0f, rsB = 0.0f;
#pragma unroll
            for (int n = 0; n < 8; n++) {
                s[n][0] = __expf(s[n][0] - mnA); rsA += s[n][0];
                s[n][1] = __expf(s[n][1] - mnA); rsA += s[n][1];
                s[n][2] = __expf(s[n][2] - mnB); rsB += s[n][2];
                s[n][3] = __expf(s[n][3] - mnB); rsB += s[n][3];
                o[n][0] *= cA; o[n][1] *= cA;
                o[n][2] *= cB; o[n][3] *= cB;
            }
            rsA += __shfl_xor_sync(0xffffffffu, rsA, 1);
            rsA += __shfl_xor_sync(0xffffffffu, rsA, 2);
            rsB += __shfl_xor_sync(0xffffffffu, rsB, 1);
            rsB += __shfl_xor_sync(0xffffffffu, rsB, 2);
            lA = lA * cA + rsA; mA = mnA;
            lB = lB * cB + rsB; mB = mnB;
        }

        // ---- P A-frags: pack accumulator pairs in-thread ----
        uint32_t ap[4][4];
#pragma unroll
        for (int kc = 0; kc < 4; kc++) {
            ap[kc][0] = pack_f16x2(s[2 * kc][0],     s[2 * kc][1]);
            ap[kc][1] = pack_f16x2(s[2 * kc][2],     s[2 * kc][3]);
            ap[kc][2] = pack_f16x2(s[2 * kc + 1][0], s[2 * kc + 1][1]);
            ap[kc][3] = pack_f16x2(s[2 * kc + 1][2], s[2 * kc + 1][3]);
        }

        // ---- O += P . V ----
#pragma unroll
        for (int n = 0; n < 8; n++) {
#pragma unroll
            for (int kc = 0; kc < 4; kc++) {
                uint32_t b0 = Vb[(kc * 8 + q) * 68 + n * 8 + g];
                uint32_t b1 = Vb[(kc * 8 + 4 + q) * 68 + n * 8 + g];
                mma_f16(o[n], ap[kc], b0, b1);
            }
        }
    }

    // ---- Epilogue: normalize, write fp16 [B,L,H*hd] ----
    {
        float iA = 1.0f / lA;
        float iB = 1.0f / lB;
        int row0 = q0 + w * 16 + g;
#pragma unroll
        for (int n = 0; n < 8; n++) {
            int col = n * 8 + 2 * q;
            uint32_t p0 = pack_f16x2(o[n][0] * iA, o[n][1] * iA);
            uint32_t p1 = pack_f16x2(o[n][2] * iB, o[n][3] * iB);
            *reinterpret_cast<uint32_t*>(
                g_attn_h + ((size_t)(b_ * SEQLEN + row0) * NHEAD + h_) * HEADDIM + col) = p0;
            *reinterpret_cast<uint32_t*>(
                g_attn_h + ((size_t)(b_ * SEQLEN + row0 + 8) * NHEAD + h_) * HEADDIM + col) = p1;
        }
    }
}

// ---------------------------------------------------------------------------
extern "C" void kernel_launch(void* const* d_in, const int* in_sizes, int n_in,
                              void* d_out, int out_size)
{
    const float* x  = (const float*)d_in[0];
    const float* Wq = (const float*)d_in[1];
    const float* bq = (const float*)d_in[2];
    const float* Wk = (const float*)d_in[3];
    const float* bk = (const float*)d_in[4];
    const float* Wv = (const float*)d_in[5];
    const float* bv = (const float*)d_in[6];
    const float* Wo = (const float*)d_in[7];
    const float* bo = (const float*)d_in[8];
    float* out = (float*)d_out;

    __half* d_xh;     cudaGetSymbolAddress((void**)&d_xh, g_xh);
    __half* d_wh;     cudaGetSymbolAddress((void**)&d_wh, g_wh);

    // fp16 conversions
    const int XN4 = MROWS * DMODEL / 4;          // 2097152
    const int WN4 = DMODEL * DMODEL / 4;         // 262144
    cvt_f16_kernel<<<XN4 / 256, 256>>>(x,  d_xh, XN4);
    cvt_f16_kernel<<<WN4 / 256, 256>>>(Wq, d_wh + 0 * (size_t)DMODEL * DMODEL, WN4);
    cvt_f16_kernel<<<WN4 / 256, 256>>>(Wk, d_wh + 1 * (size_t)DMODEL * DMODEL, WN4);
    cvt_f16_kernel<<<WN4 / 256, 256>>>(Wv, d_wh + 2 * (size_t)DMODEL * DMODEL, WN4);
    cvt_f16_kernel<<<WN4 / 256, 256>>>(Wo, d_wh + 3 * (size_t)DMODEL * DMODEL, WN4);

    dim3 ggrid(DMODEL / 128, MROWS / 128);   // (8, 64)
    gemm_f16<<<ggrid, 256>>>(d_xh, d_wh + 0 * (size_t)DMODEL * DMODEL, bq, nullptr, 0);
    gemm_f16<<<ggrid, 256>>>(d_xh, d_wh + 1 * (size_t)DMODEL * DMODEL, bk, nullptr, 1);
    gemm_f16<<<ggrid, 256>>>(d_xh, d_wh + 2 * (size_t)DMODEL * DMODEL, bv, nullptr, 2);

    rope_kernel<<<(BATCH * NHEAD * SEQLEN * 32) / 256, 256>>>();

    attn_mma_kernel<<<dim3(SEQLEN / 128, BATCH * NHEAD), 256>>>();

    gemm_f16<<<ggrid, 256>>>(nullptr, d_wh + 3 * (size_t)DMODEL * DMODEL, bo, out, 3);
}